// round 13
// baseline (speedup 1.0000x reference)
#include <cuda_runtime.h>
#include <cuda_bf16.h>
#include <cstdint>

// Shapes (fixed): z (16,256,32,32) fp32; codebook (2048,256) fp32; out like z.
#define N_ROWS 16384
#define DDIM   256
#define KCODES 2048
#define HW     1024
#define CAND_CAP (1 << 22)   // 4M coarse candidates (expect ~870K)

// Margin: worst-case coarse error ~9e-4; 2.5e-3 validated in R7-R12.
#define MARGIN 2.5e-3f

// ---------------- device scratch (no mallocs allowed) ----------------
__device__ float              g_cnorm[KCODES];
__device__ uint32_t           g_minu[N_ROWS];
__device__ unsigned long long g_best[N_ROWS];
__device__ int                g_candCount;
__device__ unsigned long long g_cand[CAND_CAP];        // (coarse_bf16<<32)|(n<<11)|k
__device__ float              g_zt [N_ROWS * DDIM];    // token-major fp32 z
__device__ __nv_bfloat16      g_ztb[N_ROWS * DDIM];    // token-major bf16 z
__device__ __nv_bfloat16      g_cbb[KCODES * DDIM];    // bf16 codebook

// ---------------- small helpers ----------------
__device__ __forceinline__ uint32_t cvt_bf16x2(float a, float b) {  // lo=a, hi=b
    uint32_t r;
    asm("cvt.rn.bf16x2.f32 %0, %1, %2;" : "=r"(r) : "f"(b), "f"(a));
    return r;
}
__device__ __forceinline__ uint32_t fmap(float f) {
    uint32_t b = __float_as_uint(f);
    return (b & 0x80000000u) ? ~b : (b | 0x80000000u);
}
__device__ __forceinline__ float funmap(uint32_t u) {
    uint32_t b = (u & 0x80000000u) ? (u & 0x7fffffffu) : ~u;
    return __uint_as_float(b);
}
__device__ __forceinline__ void ldsm4(uint32_t& r0, uint32_t& r1, uint32_t& r2,
                                      uint32_t& r3, uint32_t addr) {
    asm volatile("ldmatrix.sync.aligned.m8n8.x4.shared.b16 {%0,%1,%2,%3}, [%4];"
                 : "=r"(r0), "=r"(r1), "=r"(r2), "=r"(r3) : "r"(addr));
}
__device__ __forceinline__ uint32_t smem_u32(const void* p) {
    uint32_t a;
    asm("{ .reg .u64 t; cvta.to.shared.u64 t, %1; cvt.u32.u64 %0, t; }" : "=r"(a) : "l"(p));
    return a;
}
__device__ __forceinline__ void mma16816(float* c, uint32_t a0, uint32_t a1,
                                         uint32_t a2, uint32_t a3,
                                         uint32_t b0, uint32_t b1) {
    asm volatile(
        "mma.sync.aligned.m16n8k16.row.col.f32.bf16.bf16.f32 "
        "{%0,%1,%2,%3}, {%4,%5,%6,%7}, {%8,%9}, {%0,%1,%2,%3};"
        : "+f"(c[0]), "+f"(c[1]), "+f"(c[2]), "+f"(c[3])
        : "r"(a0), "r"(a1), "r"(a2), "r"(a3), "r"(b0), "r"(b1));
}
__device__ __forceinline__ void cp16(uint32_t dst, const void* src) {
    asm volatile("cp.async.cg.shared.global [%0], [%1], 16;" :: "r"(dst), "l"(src));
}

// ---------------- (1) prep: vectorized transpose + init + cbcnorm -----------
// Transpose: 64p x 64d tiles, float4 in/out. CTAs [0,1024): transpose;
// [1024,1088): init; [1088,1096): cbcnorm.
#define PREP_T_CTAS 1024
#define PREP_I_CTAS 64
#define PREP_GRID   (PREP_T_CTAS + PREP_I_CTAS + 8)
#define TPITCH 68   // floats; 68%4==0 keeps float4 smem stores aligned

__global__ void __launch_bounds__(256) prep_kernel(const float* __restrict__ z,
                                                   const float* __restrict__ cb) {
    const int bx = blockIdx.x, t = threadIdx.x;
    if (bx < PREP_T_CTAS) {
        __shared__ float ts[64][TPITCH];
        const int b  = bx >> 6;
        const int rest = bx & 63;
        const int pt = rest & 15, dt = rest >> 4;
        const int p0 = pt * 64, d0 = dt * 64;
        // load: 64 d-rows x 16 float4 p-columns
        #pragma unroll
        for (int it = 0; it < 4; it++) {
            int slot = it * 256 + t;
            int drow = slot >> 4, pc = slot & 15;
            float4 v = *reinterpret_cast<const float4*>(
                &z[((size_t)(b * DDIM + d0 + drow)) * HW + p0 + pc * 4]);
            *reinterpret_cast<float4*>(&ts[drow][pc * 4]) = v;
        }
        __syncthreads();
        // store: 64 token-rows x 16 float4 d-columns (exact fp32 copy + bf16)
        #pragma unroll
        for (int it = 0; it < 4; it++) {
            int slot = it * 256 + t;
            int prow = slot >> 4, dc = slot & 15;
            float f0 = ts[dc * 4 + 0][prow];
            float f1 = ts[dc * 4 + 1][prow];
            float f2 = ts[dc * 4 + 2][prow];
            float f3 = ts[dc * 4 + 3][prow];
            int n = b * HW + p0 + prow;
            *reinterpret_cast<float4*>(&g_zt[(size_t)n * DDIM + d0 + dc * 4]) =
                make_float4(f0, f1, f2, f3);
            uint2 bb = make_uint2(cvt_bf16x2(f0, f1), cvt_bf16x2(f2, f3));
            *reinterpret_cast<uint2*>(&g_ztb[(size_t)n * DDIM + d0 + dc * 4]) = bb;
        }
    } else if (bx < PREP_T_CTAS + PREP_I_CTAS) {
        int n = (bx - PREP_T_CTAS) * 256 + t;
        g_minu[n] = 0xFFFFFFFFu;
        g_best[n] = 0xFFFFFFFFFFFFFFFFull;
        if (n == 0) g_candCount = 0;
    } else {
        int k = (bx - PREP_T_CTAS - PREP_I_CTAS) * 256 + t;
        const float4* row4 = reinterpret_cast<const float4*>(cb + (size_t)k * DDIM);
        uint32_t* out = reinterpret_cast<uint32_t*>(g_cbb + (size_t)k * DDIM);
        float s = 0.f;
        #pragma unroll 4
        for (int d4 = 0; d4 < DDIM / 4; d4++) {
            float4 v = row4[d4];
            s = __fmaf_rn(v.x, v.x, s);   // sequential chain (matched JAX 10x)
            s = __fmaf_rn(v.y, v.y, s);
            s = __fmaf_rn(v.z, v.z, s);
            s = __fmaf_rn(v.w, v.w, s);
            out[d4 * 2 + 0] = cvt_bf16x2(v.x, v.y);
            out[d4 * 2 + 1] = cvt_bf16x2(v.z, v.w);
        }
        g_cnorm[k] = s;
    }
}

// ---------------- (2) coarse GEMM: 3-stage cp.async + emission (as R12) -----
#define PITCH 72
#define A_BYTES (128 * PITCH * 2)        // 18432
#define STAGE_BYTES (2 * A_BYTES)        // 36864 (A + B per stage)
#define NSTAGE 3
#define MMA_SMEM (NSTAGE * STAGE_BYTES)  // 110592 dynamic

__global__ void __launch_bounds__(256, 2) mma_kernel() {
    extern __shared__ __align__(16) char dsm[];
    __shared__ int s_cnt, s_base;

    const int t = threadIdx.x, wid = t >> 5, lane = t & 31;
    const int row0 = blockIdx.x * 128, col0 = blockIdx.y * 128;
    const int wm = (wid & 3) * 32;
    const int wn = (wid >> 2) * 64;
    const int r  = lane >> 2, tt = lane & 3;
    const int grp = lane >> 3, l7 = lane & 7;

    const int a_row = (grp & 1) * 8 + l7, a_k = (grp & 2) * 4;
    const int b_row = (grp & 2) * 4 + l7, b_k = (grp & 1) * 8;
    const uint32_t sbase = smem_u32(dsm);
    uint32_t aOff[2], bOff[4];                   // stage-relative
    #pragma unroll
    for (int mt = 0; mt < 2; mt++)
        aOff[mt] = ((wm + mt * 16 + a_row) * PITCH + a_k) * 2;
    #pragma unroll
    for (int p = 0; p < 4; p++)
        bOff[p] = A_BYTES + ((wn + p * 16 + b_row) * PITCH + b_k) * 2;

    float acc[2][8][4];
    #pragma unroll
    for (int mt = 0; mt < 2; mt++)
        #pragma unroll
        for (int nt = 0; nt < 8; nt++)
            #pragma unroll
            for (int q = 0; q < 4; q++) acc[mt][nt][q] = 0.f;

    auto prefetch = [&](int ch) {
        const int s = ch % NSTAGE, cd0 = ch * 64;
        const uint32_t abuf = sbase + s * STAGE_BYTES;
        const uint32_t bbuf = abuf + A_BYTES;
        #pragma unroll
        for (int it = 0; it < 4; it++) {
            int idx = it * 256 + t;
            int rr = idx >> 3, k8 = (idx & 7) * 8;
            uint32_t off = (rr * PITCH + k8) * 2;
            cp16(abuf + off, &g_ztb[(size_t)(row0 + rr) * DDIM + cd0 + k8]);
            cp16(bbuf + off, &g_cbb[(size_t)(col0 + rr) * DDIM + cd0 + k8]);
        }
        asm volatile("cp.async.commit_group;" ::: "memory");
    };

    prefetch(0);
    prefetch(1);
    for (int ch = 0; ch < 4; ch++) {
        if (ch < 3) asm volatile("cp.async.wait_group 1;" ::: "memory");
        else        asm volatile("cp.async.wait_group 0;" ::: "memory");
        __syncthreads();
        if (ch < 2) prefetch(ch + 2);

        const uint32_t sb = sbase + (ch % NSTAGE) * STAGE_BYTES;
        #pragma unroll
        for (int ks = 0; ks < 4; ks++) {
            const uint32_t koff = ks * 32;
            uint32_t A0[4], A1[4];
            ldsm4(A0[0], A0[1], A0[2], A0[3], sb + aOff[0] + koff);
            ldsm4(A1[0], A1[1], A1[2], A1[3], sb + aOff[1] + koff);
            #pragma unroll
            for (int p = 0; p < 4; p++) {
                uint32_t B[4];
                ldsm4(B[0], B[1], B[2], B[3], sb + bOff[p] + koff);
                mma16816(acc[0][2 * p],     A0[0], A0[1], A0[2], A0[3], B[0], B[1]);
                mma16816(acc[0][2 * p + 1], A0[0], A0[1], A0[2], A0[3], B[2], B[3]);
                mma16816(acc[1][2 * p],     A1[0], A1[1], A1[2], A1[3], B[0], B[1]);
                mma16816(acc[1][2 * p + 1], A1[0], A1[1], A1[2], A1[3], B[2], B[3]);
            }
        }
    }
    __syncthreads();

    // --- epilogue: coarse = cnorm - 2*dot; warp row mins; emission ---
    float rmin[2][2];
    #pragma unroll
    for (int mt = 0; mt < 2; mt++) { rmin[mt][0] = 3.4e38f; rmin[mt][1] = 3.4e38f; }
    #pragma unroll
    for (int mt = 0; mt < 2; mt++)
        #pragma unroll
        for (int nt = 0; nt < 8; nt++) {
            const int cbase = col0 + wn + nt * 8;
            float2 cn = *reinterpret_cast<const float2*>(&g_cnorm[cbase + tt * 2]);
            float d0 = __fmaf_rn(-2.f, acc[mt][nt][0], cn.x);
            float d1 = __fmaf_rn(-2.f, acc[mt][nt][1], cn.y);
            float d2 = __fmaf_rn(-2.f, acc[mt][nt][2], cn.x);
            float d3 = __fmaf_rn(-2.f, acc[mt][nt][3], cn.y);
            acc[mt][nt][0] = d0; acc[mt][nt][1] = d1;
            acc[mt][nt][2] = d2; acc[mt][nt][3] = d3;
            rmin[mt][0] = fminf(rmin[mt][0], fminf(d0, d1));
            rmin[mt][1] = fminf(rmin[mt][1], fminf(d2, d3));
        }
    #pragma unroll
    for (int mt = 0; mt < 2; mt++)
        #pragma unroll
        for (int h = 0; h < 2; h++)
            #pragma unroll
            for (int off = 1; off < 4; off <<= 1)
                rmin[mt][h] = fminf(rmin[mt][h],
                                    __shfl_xor_sync(0xffffffffu, rmin[mt][h], off));

    float gmv[2][2];
    if (tt == 0) {
        #pragma unroll
        for (int mt = 0; mt < 2; mt++) {
            const int grow = row0 + wm + mt * 16 + r;
            uint32_t o0 = atomicMin(&g_minu[grow],     fmap(rmin[mt][0]));
            uint32_t o1 = atomicMin(&g_minu[grow + 8], fmap(rmin[mt][1]));
            gmv[mt][0] = funmap(o0);   // NaN if untouched; fminf ignores NaN
            gmv[mt][1] = funmap(o1);
        }
    }
    const int src = lane & ~3;
    float th[2][2];
    #pragma unroll
    for (int mt = 0; mt < 2; mt++)
        #pragma unroll
        for (int h = 0; h < 2; h++) {
            float g = __shfl_sync(0xffffffffu, gmv[mt][h], src);
            th[mt][h] = fminf(rmin[mt][h], g) + (MARGIN + 1e-4f);
        }

    if (t == 0) s_cnt = 0;
    int cnt = 0;
    #pragma unroll
    for (int mt = 0; mt < 2; mt++)
        #pragma unroll
        for (int nt = 0; nt < 8; nt++)
            #pragma unroll
            for (int q = 0; q < 4; q++)
                cnt += (acc[mt][nt][q] <= th[mt][q >> 1]) ? 1 : 0;

    int pref = cnt;
    #pragma unroll
    for (int off = 1; off < 32; off <<= 1) {
        int v = __shfl_up_sync(0xffffffffu, pref, off);
        if (lane >= off) pref += v;
    }
    int excl = pref - cnt;
    __syncthreads();
    int wbase = 0;
    if (lane == 31) wbase = atomicAdd(&s_cnt, pref);
    wbase = __shfl_sync(0xffffffffu, wbase, 31);
    __syncthreads();
    if (t == 0) s_base = s_cnt ? atomicAdd(&g_candCount, s_cnt) : 0;
    __syncthreads();
    int pos = s_base + wbase + excl;

    #pragma unroll
    for (int mt = 0; mt < 2; mt++)
        #pragma unroll
        for (int nt = 0; nt < 8; nt++)
            #pragma unroll
            for (int q = 0; q < 4; q++) {
                float d = acc[mt][nt][q];
                if (d <= th[mt][q >> 1]) {
                    if (pos < CAND_CAP) {
                        int grow = row0 + wm + mt * 16 + r + ((q >> 1) ? 8 : 0);
                        int k    = col0 + wn + nt * 8 + tt * 2 + (q & 1);
                        uint32_t dbits =
                            (uint32_t)__bfloat16_as_ushort(__float2bfloat16(d));
                        g_cand[pos] = ((unsigned long long)dbits << 32)
                                    | ((uint32_t)grow << 11) | (uint32_t)k;
                    }
                    pos++;
                }
            }
}

// ---------------- (3) rescore: inline filter + exact chain (as R11/R12) -----
#define RS_GRID 1024

__global__ void __launch_bounds__(256) rescore_kernel(const float* __restrict__ cb) {
    int total = g_candCount; if (total > CAND_CAP) total = CAND_CAP;
    for (int i = blockIdx.x * 256 + threadIdx.x; i < total; i += RS_GRID * 256) {
        unsigned long long e = g_cand[i];
        uint32_t nk = (uint32_t)e & 0x1FFFFFFu;
        int n = nk >> 11, k = nk & 2047;
        float coarse =
            __bfloat162float(__ushort_as_bfloat16((unsigned short)(e >> 32)));
        if (coarse <= funmap(g_minu[n]) + MARGIN) {
            const float4* za4 = reinterpret_cast<const float4*>(g_zt + (size_t)n * DDIM);
            const float4* ca4 = reinterpret_cast<const float4*>(cb + (size_t)k * DDIM);
            float acc = 0.f, zn = 0.f;
            #pragma unroll 8
            for (int d4 = 0; d4 < DDIM / 4; d4++) {
                float4 a = za4[d4], c = ca4[d4];
                zn  = __fmaf_rn(a.x, a.x, zn);    // znorm chain (verified 10x)
                zn  = __fmaf_rn(a.y, a.y, zn);
                zn  = __fmaf_rn(a.z, a.z, zn);
                zn  = __fmaf_rn(a.w, a.w, zn);
                acc = __fmaf_rn(a.x, c.x, acc);   // dot chain (verified 10x)
                acc = __fmaf_rn(a.y, c.y, acc);
                acc = __fmaf_rn(a.z, c.z, acc);
                acc = __fmaf_rn(a.w, c.w, acc);
            }
            float dist = __fadd_rn(__fadd_rn(zn, g_cnorm[k]), -2.0f * acc);
            unsigned long long pk =
                ((unsigned long long)__float_as_uint(dist) << 32) | (unsigned)k;
            atomicMin(&g_best[n], pk);
        }
    }
}

// ---------------- (4) gather + STE with smem-staged codebook rows ----------
#define GT 32   // tokens per CTA

__global__ void __launch_bounds__(256) gather_kernel(const float* __restrict__ z,
                                                     const float* __restrict__ cb,
                                                     float* __restrict__ out) {
    __shared__ float cbrow[GT][DDIM + 1];
    __shared__ int ks[GT];
    const int t = threadIdx.x;
    const int n0 = blockIdx.x * GT;
    const int b = n0 >> 10, p0 = n0 & 1023;

    if (t < GT) ks[t] = (int)(g_best[n0 + t] & 0xffffffffu);
    __syncthreads();

    #pragma unroll
    for (int it = 0; it < (GT * DDIM / 4) / 256; it++) {
        int slot = it * 256 + t;
        int tok = slot >> 6, c4 = slot & 63;
        float4 v = reinterpret_cast<const float4*>(cb + (size_t)ks[tok] * DDIM)[c4];
        cbrow[tok][c4 * 4 + 0] = v.x;
        cbrow[tok][c4 * 4 + 1] = v.y;
        cbrow[tok][c4 * 4 + 2] = v.z;
        cbrow[tok][c4 * 4 + 3] = v.w;
    }
    __syncthreads();

    const size_t zbase = (size_t)b * DDIM * HW + p0;
    #pragma unroll
    for (int it = 0; it < 8; it++) {
        int slot = it * 256 + t;
        int d = slot >> 3, p4 = slot & 7;
        size_t off = zbase + (size_t)d * HW + p4 * 4;
        float4 zv = *reinterpret_cast<const float4*>(z + off);
        float q0 = cbrow[p4 * 4 + 0][d];
        float q1 = cbrow[p4 * 4 + 1][d];
        float q2 = cbrow[p4 * 4 + 2][d];
        float q3 = cbrow[p4 * 4 + 3][d];
        float4 r;
        r.x = __fadd_rn(zv.x, __fadd_rn(q0, -zv.x));   // STE chain (matched 10x)
        r.y = __fadd_rn(zv.y, __fadd_rn(q1, -zv.y));
        r.z = __fadd_rn(zv.z, __fadd_rn(q2, -zv.z));
        r.w = __fadd_rn(zv.w, __fadd_rn(q3, -zv.w));
        *reinterpret_cast<float4*>(out + off) = r;
    }
}

// ---------------------------------------------------------------------------
extern "C" void kernel_launch(void* const* d_in, const int* in_sizes, int n_in,
                              void* d_out, int out_size) {
    const float* z  = (const float*)d_in[0];
    const float* cb = (const float*)d_in[1];
    float* out = (float*)d_out;

    cudaFuncSetAttribute(mma_kernel,
                         cudaFuncAttributeMaxDynamicSharedMemorySize, MMA_SMEM);

    prep_kernel<<<PREP_GRID, 256>>>(z, cb);                            // 1
    mma_kernel<<<dim3(N_ROWS / 128, KCODES / 128), 256, MMA_SMEM>>>(); // 2
    rescore_kernel<<<RS_GRID, 256>>>(cb);                              // 3
    gather_kernel<<<N_ROWS / GT, 256>>>(z, cb, out);                   // 4
}